// round 8
// baseline (speedup 1.0000x reference)
#include <cuda_runtime.h>
#include <cstdint>

#define DD      512
#define HK      2048
#define NB      1024
#define LSLOTS  50
#define KSW     16           // split-K for W gemm
#define KST     8            // split-K for temp gemm
#define NBLK    256          // compute blocks participating in grid barrier
#define N4ALL   (LSLOTS * NB * DD / 4)   // 6,553,600 float4
#define GSTRIDE (NBLK * 256)             // 65536 threads

// Scratch (static device globals — no allocation)
__device__ float g_Wpart[KSW * DD * DD];     // split-K partials of Wt[j,a] (16 MB)
__device__ float g_W[DD * DD];               // Wt[j][a] = (wv@wo)[a][j]
__device__ float g_c[DD];                    // bv@wo + bo
__device__ float g_Tpart[KST * NB * DD];     // split-K partials (16 MB)
__device__ float g_temp[NB * DD];            // 3w*(hid@W + c)

// grid barrier state (generation persists across replays; monotone)
__device__ int g_bar_count = 0;
__device__ volatile int g_bar_gen = 0;

__device__ __forceinline__ void grid_bar() {
    __syncthreads();
    if (threadIdx.x == 0) {
        __threadfence();
        int gen = g_bar_gen;
        if (atomicAdd(&g_bar_count, 1) == NBLK - 1) {
            g_bar_count = 0;
            __threadfence();
            g_bar_gen = gen + 1;
        } else {
            while (g_bar_gen == gen) { }
        }
        __threadfence();
    }
    __syncthreads();
}

// ---------------------------------------------------------------------------
// helpers
// ---------------------------------------------------------------------------
__device__ __forceinline__ uint32_t f2tf(float x) {
    uint32_t r; asm("cvt.rna.tf32.f32 %0, %1;" : "=r"(r) : "f"(x)); return r;
}
__device__ __forceinline__ void mma8(float* d, const uint32_t* a, const uint32_t* b) {
    asm volatile(
        "mma.sync.aligned.m16n8k8.row.col.f32.tf32.tf32.f32 "
        "{%0,%1,%2,%3}, {%4,%5,%6,%7}, {%8,%9}, {%0,%1,%2,%3};"
        : "+f"(d[0]), "+f"(d[1]), "+f"(d[2]), "+f"(d[3])
        : "r"(a[0]), "r"(a[1]), "r"(a[2]), "r"(a[3]), "r"(b[0]), "r"(b[1]));
}

// ---------------------------------------------------------------------------
// TF32 mma.sync GEMM device fn: C[z][m,n] = sum_{k in chunk z} A[m,k]*B[n,k]
//   ATR=false: A row-major [m][LDA] K-contig; ATR=true: A is [k][LDA] m-contig.
// Tile 128x128, Kc=32 per stage, double-buffered smem, 256 threads / 8 warps.
// Partials stored with __stwt (write-through: no dirty L2 lines).
// ---------------------------------------------------------------------------
#define ASZ    4608          // 128*36 words (ATR uses 32*132=4224 of it)
#define BSZ    4608
#define STAGE  (ASZ + BSZ)
#define SMEM_WORDS (2 * STAGE)
#define SMEM_BYTES (SMEM_WORDS * 4)

template<bool ATR, int LDA, int LDB, int MTOT, int NTOT, int KCHUNK>
__device__ __forceinline__ void gemm_dev(const float* __restrict__ Ag,
                                         const float* __restrict__ Bg,
                                         float* __restrict__ C,
                                         uint32_t* smem,
                                         int bx, int by, int bz) {
    const int t = threadIdx.x;
    const int nBase = bx * 128;
    const int mBase = by * 128;
    const int kb    = bz * KCHUNK;

    const bool isA = (t < 128);
    const int tt = t & 127;
    const int rr = tt >> 3;
    const int fc = tt & 7;
    const int jq = tt & 31;
    const int kr = tt >> 5;

    constexpr int NS = KCHUNK / 32;
    float4 rg[8];

#define LDG(s)                                                                  \
    {                                                                           \
        if (isA) {                                                              \
            if (ATR) {                                                          \
                _Pragma("unroll")                                               \
                for (int i = 0; i < 8; ++i)                                     \
                    rg[i] = *(const float4*)&Ag[(size_t)(kb + (s)*32 + kr + 4*i) * LDA \
                                                + mBase + jq * 4];              \
            } else {                                                            \
                _Pragma("unroll")                                               \
                for (int i = 0; i < 8; ++i)                                     \
                    rg[i] = *(const float4*)&Ag[(size_t)(mBase + rr + 16*i) * LDA \
                                                + kb + (s)*32 + fc * 4];        \
            }                                                                   \
        } else {                                                                \
            _Pragma("unroll")                                                   \
            for (int i = 0; i < 8; ++i)                                         \
                rg[i] = *(const float4*)&Bg[(size_t)(nBase + rr + 16*i) * LDB   \
                                            + kb + (s)*32 + fc * 4];            \
        }                                                                       \
    }

    const int w = t >> 5, lane = t & 31;
    const int moff = (w & 3) * 32;
    const int noff = (w >> 2) * 64;
    const int g = lane >> 2, q = lane & 3;

    float acc[2][8][4];
#pragma unroll
    for (int mt = 0; mt < 2; mt++)
#pragma unroll
        for (int nt = 0; nt < 8; nt++)
#pragma unroll
            for (int r = 0; r < 4; r++) acc[mt][nt][r] = 0.0f;

    LDG(0);

    for (int s = 0; s < NS; ++s) {
        const int buf = s & 1;
        uint32_t* dst = smem + buf * STAGE + (isA ? 0 : ASZ);
        if (isA && ATR) {
#pragma unroll
            for (int i = 0; i < 8; ++i) {
                uint32_t* p = dst + (kr + 4 * i) * 132 + jq * 4;
                p[0] = f2tf(rg[i].x); p[1] = f2tf(rg[i].y);
                p[2] = f2tf(rg[i].z); p[3] = f2tf(rg[i].w);
            }
        } else {
#pragma unroll
            for (int i = 0; i < 8; ++i) {
                uint32_t* p = dst + (rr + 16 * i) * 36 + fc * 4;
                p[0] = f2tf(rg[i].x); p[1] = f2tf(rg[i].y);
                p[2] = f2tf(rg[i].z); p[3] = f2tf(rg[i].w);
            }
        }
        __syncthreads();
        if (s + 1 < NS) LDG(s + 1);

        const uint32_t* As = smem + buf * STAGE;
        const uint32_t* Bs = As + ASZ;
#pragma unroll
        for (int k0 = 0; k0 < 32; k0 += 8) {
            uint32_t af[2][4];
#pragma unroll
            for (int mt = 0; mt < 2; mt++) {
                const int m0 = moff + mt * 16 + g;
                if (ATR) {
                    af[mt][0] = As[(k0 + q) * 132 + m0];
                    af[mt][1] = As[(k0 + q) * 132 + m0 + 8];
                    af[mt][2] = As[(k0 + q + 4) * 132 + m0];
                    af[mt][3] = As[(k0 + q + 4) * 132 + m0 + 8];
                } else {
                    af[mt][0] = As[m0 * 36 + k0 + q];
                    af[mt][1] = As[(m0 + 8) * 36 + k0 + q];
                    af[mt][2] = As[m0 * 36 + k0 + q + 4];
                    af[mt][3] = As[(m0 + 8) * 36 + k0 + q + 4];
                }
            }
            uint32_t bf[8][2];
#pragma unroll
            for (int nt = 0; nt < 8; nt++) {
                const int n0 = noff + nt * 8 + g;
                bf[nt][0] = Bs[n0 * 36 + k0 + q];
                bf[nt][1] = Bs[n0 * 36 + k0 + q + 4];
            }
#pragma unroll
            for (int mt = 0; mt < 2; mt++)
#pragma unroll
                for (int nt = 0; nt < 8; nt++)
                    mma8(acc[mt][nt], af[mt], bf[nt]);
        }
        __syncthreads();
    }
#undef LDG

    float* cz = C + (size_t)bz * MTOT * NTOT;
#pragma unroll
    for (int mt = 0; mt < 2; mt++) {
        const int r0 = mBase + moff + mt * 16 + g;
#pragma unroll
        for (int nt = 0; nt < 8; nt++) {
            const int c0 = nBase + noff + nt * 8 + q * 2;
            float2 v0 = make_float2(acc[mt][nt][0], acc[mt][nt][1]);
            float2 v1 = make_float2(acc[mt][nt][2], acc[mt][nt][3]);
            __stwt((float2*)&cz[(size_t)r0 * NTOT + c0], v0);
            __stwt((float2*)&cz[(size_t)(r0 + 8) * NTOT + c0], v1);
        }
    }
}

// ---------------------------------------------------------------------------
// Single fused persistent kernel, 256 blocks, 2 blocks/SM.
// P0 gemm_w | P1 reduce_w + bias_c | P2 gemm_temp | P3 reduce_temp |
// P4 out = momery + temp (streaming add).
// ---------------------------------------------------------------------------
#define BD4 (NB * DD / 4)   // 131072, power of two

__global__ __launch_bounds__(256, 2) void k_fused(const float* __restrict__ wo,
                                                  const float* __restrict__ wv,
                                                  const float* __restrict__ hid,
                                                  const float* __restrict__ bv,
                                                  const float* __restrict__ bo,
                                                  const float* __restrict__ wsc,
                                                  const float4* __restrict__ mom,
                                                  float4* __restrict__ out) {
    extern __shared__ uint32_t smem[];
    __shared__ float sred[8];
    const int b = blockIdx.x;
    const int t = threadIdx.x;

    // ---- P0: Wt partials  Wt[j,a] = sum_k wo[k,j] * wv[a,k]
    gemm_dev<true, DD, HK, DD, DD, HK / KSW>(wo, wv, g_Wpart, smem,
                                             b & 3, (b >> 2) & 3, b >> 4);
    grid_bar();

    // ---- P1a: reduce W partials (65536 float4 over 256 blocks => 1/thread)
    {
        const float4* p = (const float4*)g_Wpart;
        int i = b * 256 + t;
        float4 s = p[i];
#pragma unroll
        for (int k = 1; k < KSW; k++) {
            float4 v = p[k * (DD * DD / 4) + i];
            s.x += v.x; s.y += v.y; s.z += v.z; s.w += v.w;
        }
        ((float4*)g_W)[i] = s;
    }
    // ---- P1b: bias c[j] = sum_k bv[k]*wo[k,j] + bo[j]  (2 j's per block)
    {
        const int jloc = t >> 7;               // 0..1
        const int j = b * 2 + jloc;
        const int tk = t & 127;
        float acc = 0.0f;
        const int k0 = tk * 16;
        for (int k = k0; k < k0 + 16; k++)
            acc += bv[k] * wo[(size_t)k * DD + j];
#pragma unroll
        for (int off = 16; off > 0; off >>= 1)
            acc += __shfl_down_sync(0xFFFFFFFFu, acc, off);
        if ((t & 31) == 0) sred[t >> 5] = acc;
        __syncthreads();
        if (t < 2)
            g_c[b * 2 + t] = sred[4 * t] + sred[4 * t + 1] + sred[4 * t + 2]
                           + sred[4 * t + 3] + bo[b * 2 + t];
    }
    grid_bar();

    // ---- P2: temp partials  Tpart[z][b,j] = sum_a hid[b,a]*Wt[j,a]
    gemm_dev<false, DD, DD, NB, DD, DD / KST>(hid, g_W, g_Tpart, smem,
                                              b & 3, (b >> 2) & 7, b >> 5);
    grid_bar();

    // ---- P3: temp = 3w * (sum partials + c)   (131072 float4 => 2/thread)
    {
        const float sc = 3.0f * wsc[0];
        const float4* p = (const float4*)g_Tpart;
#pragma unroll
        for (int u = 0; u < 2; ++u) {
            int i = b * 512 + u * 256 + t;
            float4 s = p[i];
#pragma unroll
            for (int k = 1; k < KST; k++) {
                float4 v = p[k * (NB * DD / 4) + i];
                s.x += v.x; s.y += v.y; s.z += v.z; s.w += v.w;
            }
            float4 c4 = ((const float4*)g_c)[i & (DD / 4 - 1)];
            s.x = sc * (s.x + c4.x); s.y = sc * (s.y + c4.y);
            s.z = sc * (s.z + c4.z); s.w = sc * (s.w + c4.w);
            ((float4*)g_temp)[i] = s;
        }
    }
    grid_bar();

    // ---- P4: out[l,b,d] = momery[l,b,d] + temp[b,d]
    // 6,553,600 float4 = 25 iters x 4-way batch x 65536 threads (exact tiling)
    {
        const float4* tp = (const float4*)g_temp;
        const int tid = b * 256 + t;
#pragma unroll 1
        for (int k = 0; k < 25; ++k) {
            const int i0 = tid + k * (4 * GSTRIDE);
            const int i1 = i0 + GSTRIDE;
            const int i2 = i0 + 2 * GSTRIDE;
            const int i3 = i0 + 3 * GSTRIDE;
            float4 m0 = __ldcs(&mom[i0]);
            float4 m1 = __ldcs(&mom[i1]);
            float4 m2 = __ldcs(&mom[i2]);
            float4 m3 = __ldcs(&mom[i3]);
            float4 t0 = tp[i0 & (BD4 - 1)];
            float4 t1 = tp[i1 & (BD4 - 1)];
            float4 t2 = tp[i2 & (BD4 - 1)];
            float4 t3 = tp[i3 & (BD4 - 1)];
            m0.x += t0.x; m0.y += t0.y; m0.z += t0.z; m0.w += t0.w;
            m1.x += t1.x; m1.y += t1.y; m1.z += t1.z; m1.w += t1.w;
            m2.x += t2.x; m2.y += t2.y; m2.z += t2.z; m2.w += t2.w;
            m3.x += t3.x; m3.y += t3.y; m3.z += t3.z; m3.w += t3.w;
            __stcs(&out[i0], m0);
            __stcs(&out[i1], m1);
            __stcs(&out[i2], m2);
            __stcs(&out[i3], m3);
        }
    }
}

// ---------------------------------------------------------------------------
// Launch. Inputs (metadata order):
// 0 momery, 1 hid, 2 text_polarity, 3 attribute_polarity, 4 w,
// 5 p_w1, 6 p_b1, 7 p_w2, 8 p_b2, 9 wq, 10 bq, 11 wk, 12 bk,
// 13 wv, 14 bv, 15 wo, 16 bo
// ---------------------------------------------------------------------------
extern "C" void kernel_launch(void* const* d_in, const int* in_sizes, int n_in,
                              void* d_out, int out_size) {
    const float* momery = (const float*)d_in[0];
    const float* hid    = (const float*)d_in[1];
    const float* w      = (const float*)d_in[4];
    const float* wv     = (const float*)d_in[13];
    const float* bv     = (const float*)d_in[14];
    const float* wo     = (const float*)d_in[15];
    const float* bo     = (const float*)d_in[16];
    float* out = (float*)d_out;

    cudaFuncSetAttribute(k_fused, cudaFuncAttributeMaxDynamicSharedMemorySize,
                         SMEM_BYTES);

    k_fused<<<NBLK, 256, SMEM_BYTES>>>(wo, wv, hid, bv, bo, w,
                                       (const float4*)momery, (float4*)out);
}

// round 9
// speedup vs baseline: 1.0275x; 1.0275x over previous
#include <cuda_runtime.h>
#include <cstdint>

#define DD      512
#define HK      2048
#define NB      1024
#define LSLOTS  50
#define KSW     16           // split-K for W gemm
#define KST     8            // split-K for temp gemm
#define NBLK    256          // compute blocks participating in grid barrier
#define N4ALL   (LSLOTS * NB * DD / 4)   // 6,553,600 float4

// Scratch (static device globals — no allocation)
__device__ float g_Wpart[KSW * DD * DD];     // split-K partials of Wt[j,a] (16 MB)
__device__ float g_W[DD * DD];               // Wt[j][a] = (wv@wo)[a][j]
__device__ float g_c[DD];                    // bv@wo + bo
__device__ float g_Tpart[KST * NB * DD];     // split-K partials (16 MB)
__device__ float g_temp[NB * DD];            // 3w*(hid@W + c)

// grid barrier state (generation persists across replays; monotone)
__device__ int g_bar_count = 0;
__device__ volatile int g_bar_gen = 0;

__device__ __forceinline__ void grid_bar() {
    __syncthreads();
    if (threadIdx.x == 0) {
        __threadfence();
        int gen = g_bar_gen;
        if (atomicAdd(&g_bar_count, 1) == NBLK - 1) {
            g_bar_count = 0;
            __threadfence();
            g_bar_gen = gen + 1;
        } else {
            while (g_bar_gen == gen) { }
        }
        __threadfence();
    }
    __syncthreads();
}

// ---------------------------------------------------------------------------
// helpers
// ---------------------------------------------------------------------------
__device__ __forceinline__ uint32_t f2tf(float x) {
    uint32_t r; asm("cvt.rna.tf32.f32 %0, %1;" : "=r"(r) : "f"(x)); return r;
}
__device__ __forceinline__ void mma8(float* d, const uint32_t* a, const uint32_t* b) {
    asm volatile(
        "mma.sync.aligned.m16n8k8.row.col.f32.tf32.tf32.f32 "
        "{%0,%1,%2,%3}, {%4,%5,%6,%7}, {%8,%9}, {%0,%1,%2,%3};"
        : "+f"(d[0]), "+f"(d[1]), "+f"(d[2]), "+f"(d[3])
        : "r"(a[0]), "r"(a[1]), "r"(a[2]), "r"(a[3]), "r"(b[0]), "r"(b[1]));
}

// ---------------------------------------------------------------------------
// TF32 mma.sync GEMM device fn: C[z][m,n] = sum_{k in chunk z} A[m,k]*B[n,k]
//   ATR=false: A row-major [m][LDA] K-contig; ATR=true: A is [k][LDA] m-contig.
// Tile 128x128, Kc=32 per stage, double-buffered smem, 256 threads / 8 warps.
//
// Smem layouts (bank-conflict-free):
//   std (A-std, B): 32-word rows, word(k) swizzled by k ^ ((row&7)*4).
//     reads: bank = (k0+q) ^ (4g), distinct across all 32 lanes.
//   ATR A: [k][136]: read bank = 8q + g (mod 32), all distinct.
// ---------------------------------------------------------------------------
#define ASZ    4352          // max(32*136 ATR, 128*32 std)
#define BSZ    4096          // 128*32
#define STAGE  (ASZ + BSZ)
#define SMEM_WORDS (2 * STAGE)
#define SMEM_BYTES (SMEM_WORDS * 4)

template<bool ATR, int LDA, int LDB, int MTOT, int NTOT, int KCHUNK>
__device__ __forceinline__ void gemm_dev(const float* __restrict__ Ag,
                                         const float* __restrict__ Bg,
                                         float* __restrict__ C,
                                         uint32_t* smem,
                                         int bx, int by, int bz) {
    const int t = threadIdx.x;
    const int nBase = bx * 128;
    const int mBase = by * 128;
    const int kb    = bz * KCHUNK;

    const bool isA = (t < 128);
    const int tt = t & 127;
    const int rr = tt >> 3;        // 0..15 (std row block)
    const int fc = tt & 7;         // float4 column
    const int jq = tt & 31;        // ATR: float4 of m
    const int kr = tt >> 5;        // ATR: 0..3 k row

    constexpr int NS = KCHUNK / 32;
    float4 rg[8];

#define LDG(s)                                                                  \
    {                                                                           \
        if (isA) {                                                              \
            if (ATR) {                                                          \
                _Pragma("unroll")                                               \
                for (int i = 0; i < 8; ++i)                                     \
                    rg[i] = *(const float4*)&Ag[(size_t)(kb + (s)*32 + kr + 4*i) * LDA \
                                                + mBase + jq * 4];              \
            } else {                                                            \
                _Pragma("unroll")                                               \
                for (int i = 0; i < 8; ++i)                                     \
                    rg[i] = *(const float4*)&Ag[(size_t)(mBase + rr + 16*i) * LDA \
                                                + kb + (s)*32 + fc * 4];        \
            }                                                                   \
        } else {                                                                \
            _Pragma("unroll")                                                   \
            for (int i = 0; i < 8; ++i)                                         \
                rg[i] = *(const float4*)&Bg[(size_t)(nBase + rr + 16*i) * LDB   \
                                            + kb + (s)*32 + fc * 4];            \
        }                                                                       \
    }

    const int w = t >> 5, lane = t & 31;
    const int moff = (w & 3) * 32;
    const int noff = (w >> 2) * 64;
    const int g = lane >> 2, q = lane & 3;

    float acc[2][8][4];
#pragma unroll
    for (int mt = 0; mt < 2; mt++)
#pragma unroll
        for (int nt = 0; nt < 8; nt++)
#pragma unroll
            for (int r = 0; r < 4; r++) acc[mt][nt][r] = 0.0f;

    LDG(0);

    for (int s = 0; s < NS; ++s) {
        const int buf = s & 1;
        uint32_t* dst = smem + buf * STAGE + (isA ? 0 : ASZ);
        if (isA && ATR) {
            // rows k = kr+4i, words jq*4..+3, stride 136
#pragma unroll
            for (int i = 0; i < 8; ++i) {
                uint32_t* p = dst + (kr + 4 * i) * 136 + jq * 4;
                p[0] = f2tf(rg[i].x); p[1] = f2tf(rg[i].y);
                p[2] = f2tf(rg[i].z); p[3] = f2tf(rg[i].w);
            }
        } else {
            // std: rows rr+16i, 32-word rows, swizzled float4 slot
            const int swz = (fc * 4) ^ ((rr & 7) * 4);
#pragma unroll
            for (int i = 0; i < 8; ++i) {
                uint32_t* p = dst + (rr + 16 * i) * 32 + swz;
                p[0] = f2tf(rg[i].x); p[1] = f2tf(rg[i].y);
                p[2] = f2tf(rg[i].z); p[3] = f2tf(rg[i].w);
            }
        }
        __syncthreads();
        if (s + 1 < NS) LDG(s + 1);

        const uint32_t* As = smem + buf * STAGE;
        const uint32_t* Bs = As + ASZ;
        const int g4 = g * 4;
#pragma unroll
        for (int k0 = 0; k0 < 32; k0 += 8) {
            uint32_t af[2][4];
#pragma unroll
            for (int mt = 0; mt < 2; mt++) {
                const int m0 = moff + mt * 16 + g;
                if (ATR) {
                    af[mt][0] = As[(k0 + q) * 136 + m0];
                    af[mt][1] = As[(k0 + q) * 136 + m0 + 8];
                    af[mt][2] = As[(k0 + q + 4) * 136 + m0];
                    af[mt][3] = As[(k0 + q + 4) * 136 + m0 + 8];
                } else {
                    const int sw0 = (k0 + q) ^ g4;
                    const int sw1 = (k0 + q + 4) ^ g4;
                    af[mt][0] = As[m0 * 32 + sw0];
                    af[mt][1] = As[(m0 + 8) * 32 + sw0];
                    af[mt][2] = As[m0 * 32 + sw1];
                    af[mt][3] = As[(m0 + 8) * 32 + sw1];
                }
            }
            uint32_t bf[8][2];
            {
                const int sw0 = (k0 + q) ^ g4;
                const int sw1 = (k0 + q + 4) ^ g4;
#pragma unroll
                for (int nt = 0; nt < 8; nt++) {
                    const int n0 = noff + nt * 8 + g;
                    bf[nt][0] = Bs[n0 * 32 + sw0];
                    bf[nt][1] = Bs[n0 * 32 + sw1];
                }
            }
#pragma unroll
            for (int mt = 0; mt < 2; mt++)
#pragma unroll
                for (int nt = 0; nt < 8; nt++)
                    mma8(acc[mt][nt], af[mt], bf[nt]);
        }
        __syncthreads();
    }
#undef LDG

    float* cz = C + (size_t)bz * MTOT * NTOT;
#pragma unroll
    for (int mt = 0; mt < 2; mt++) {
        const int r0 = mBase + moff + mt * 16 + g;
#pragma unroll
        for (int nt = 0; nt < 8; nt++) {
            const int c0 = nBase + noff + nt * 8 + q * 2;
            float2 v0 = make_float2(acc[mt][nt][0], acc[mt][nt][1]);
            float2 v1 = make_float2(acc[mt][nt][2], acc[mt][nt][3]);
            *(float2*)&cz[(size_t)r0 * NTOT + c0] = v0;
            *(float2*)&cz[(size_t)(r0 + 8) * NTOT + c0] = v1;
        }
    }
}

// ---------------------------------------------------------------------------
// Fused persistent kernel, 256 blocks, 2 blocks/SM.
// P0 gemm_w (16 tiles x 16 k-slices) | P1 reduce_w + bias_c |
// P2 gemm_temp (32 tiles x 8 k-slices) | P3 reduce_temp.
// ---------------------------------------------------------------------------
__global__ __launch_bounds__(256, 2) void k_fused(const float* __restrict__ wo,
                                                  const float* __restrict__ wv,
                                                  const float* __restrict__ hid,
                                                  const float* __restrict__ bv,
                                                  const float* __restrict__ bo,
                                                  const float* __restrict__ wsc) {
    extern __shared__ uint32_t smem[];
    __shared__ float sred[8];
    const int b = blockIdx.x;
    const int t = threadIdx.x;

    // ---- P0: Wt partials  Wt[j,a] = sum_k wo[k,j] * wv[a,k]
    gemm_dev<true, DD, HK, DD, DD, HK / KSW>(wo, wv, g_Wpart, smem,
                                             b & 3, (b >> 2) & 3, b >> 4);
    grid_bar();

    // ---- P1a: reduce W partials (65536 float4 over 256 blocks => 1/thread)
    {
        const float4* p = (const float4*)g_Wpart;
        int i = b * 256 + t;
        float4 s = p[i];
#pragma unroll
        for (int k = 1; k < KSW; k++) {
            float4 v = p[k * (DD * DD / 4) + i];
            s.x += v.x; s.y += v.y; s.z += v.z; s.w += v.w;
        }
        ((float4*)g_W)[i] = s;
    }
    // ---- P1b: bias c[j] = sum_k bv[k]*wo[k,j] + bo[j]  (2 j's per block)
    {
        const int jloc = t >> 7;               // 0..1
        const int j = b * 2 + jloc;
        const int tk = t & 127;
        float acc = 0.0f;
        const int k0 = tk * 16;
        for (int k = k0; k < k0 + 16; k++)
            acc += bv[k] * wo[(size_t)k * DD + j];
#pragma unroll
        for (int off = 16; off > 0; off >>= 1)
            acc += __shfl_down_sync(0xFFFFFFFFu, acc, off);
        if ((t & 31) == 0) sred[t >> 5] = acc;
        __syncthreads();
        if (t < 2)
            g_c[b * 2 + t] = sred[4 * t] + sred[4 * t + 1] + sred[4 * t + 2]
                           + sred[4 * t + 3] + bo[b * 2 + t];
    }
    grid_bar();

    // ---- P2: temp partials  Tpart[z][b,j] = sum_a hid[b,a]*Wt[j,a]
    gemm_dev<false, DD, DD, NB, DD, DD / KST>(hid, g_W, g_Tpart, smem,
                                              b & 3, (b >> 2) & 7, b >> 5);
    grid_bar();

    // ---- P3: temp = 3w * (sum partials + c)   (131072 float4 => 2/thread)
    {
        const float sc = 3.0f * wsc[0];
        const float4* p = (const float4*)g_Tpart;
#pragma unroll
        for (int u = 0; u < 2; ++u) {
            int i = b * 512 + u * 256 + t;
            float4 s = p[i];
#pragma unroll
            for (int k = 1; k < KST; k++) {
                float4 v = p[k * (NB * DD / 4) + i];
                s.x += v.x; s.y += v.y; s.z += v.z; s.w += v.w;
            }
            float4 c4 = ((const float4*)g_c)[i & (DD / 4 - 1)];
            s.x = sc * (s.x + c4.x); s.y = sc * (s.y + c4.y);
            s.z = sc * (s.z + c4.z); s.w = sc * (s.w + c4.w);
            ((float4*)g_temp)[i] = s;
        }
    }
}

// ---------------------------------------------------------------------------
// out[l,b,d] = momery[l,b,d] + temp[b,d]
// ---------------------------------------------------------------------------
#define BD4 (NB * DD / 4)   // 131072, power of two

__global__ __launch_bounds__(256) void k_add(const float4* __restrict__ mom,
                                             float4* __restrict__ out, int n4) {
    const float4* tp = (const float4*)g_temp;
    int stride = gridDim.x * blockDim.x;
    for (int i = blockIdx.x * blockDim.x + threadIdx.x; i < n4; i += stride) {
        float4 m = mom[i];
        float4 tv = tp[i & (BD4 - 1)];
        m.x += tv.x; m.y += tv.y; m.z += tv.z; m.w += tv.w;
        __stcs(&out[i], m);
    }
}

// ---------------------------------------------------------------------------
// Launch. Inputs (metadata order):
// 0 momery, 1 hid, 2 text_polarity, 3 attribute_polarity, 4 w,
// 5 p_w1, 6 p_b1, 7 p_w2, 8 p_b2, 9 wq, 10 bq, 11 wk, 12 bk,
// 13 wv, 14 bv, 15 wo, 16 bo
// ---------------------------------------------------------------------------
extern "C" void kernel_launch(void* const* d_in, const int* in_sizes, int n_in,
                              void* d_out, int out_size) {
    const float* momery = (const float*)d_in[0];
    const float* hid    = (const float*)d_in[1];
    const float* w      = (const float*)d_in[4];
    const float* wv     = (const float*)d_in[13];
    const float* bv     = (const float*)d_in[14];
    const float* wo     = (const float*)d_in[15];
    const float* bo     = (const float*)d_in[16];
    float* out = (float*)d_out;

    cudaFuncSetAttribute(k_fused, cudaFuncAttributeMaxDynamicSharedMemorySize,
                         SMEM_BYTES);

    k_fused<<<NBLK, 256, SMEM_BYTES>>>(wo, wv, hid, bv, bo, w);

    k_add<<<6144, 256>>>((const float4*)momery, (float4*)out, N4ALL);
}

// round 10
// speedup vs baseline: 1.0968x; 1.0674x over previous
#include <cuda_runtime.h>
#include <cstdint>

#define DD      512
#define HK      2048
#define NB      1024
#define LSLOTS  50
#define KSW     16           // split-K for W gemm
#define KST     8            // split-K for temp gemm
#define NBLK    256          // compute blocks participating in grid barrier
#define BD4     (NB * DD / 4)            // 131072 float4 per L-slot

// Scratch (static device globals — no allocation)
__device__ float g_Wpart[KSW * DD * DD];     // split-K partials of Wt[j,a] (16 MB)
__device__ float g_W[DD * DD];               // Wt[j][a] = (wv@wo)[a][j]
__device__ float g_c[DD];                    // bv@wo + bo
__device__ float g_Tpart[KST * NB * DD];     // split-K partials (16 MB)

// grid barrier state (generation persists across replays; monotone)
__device__ int g_bar_count = 0;
__device__ volatile int g_bar_gen = 0;

__device__ __forceinline__ void grid_bar() {
    __syncthreads();
    if (threadIdx.x == 0) {
        __threadfence();
        int gen = g_bar_gen;
        if (atomicAdd(&g_bar_count, 1) == NBLK - 1) {
            g_bar_count = 0;
            __threadfence();
            g_bar_gen = gen + 1;
        } else {
            while (g_bar_gen == gen) { __nanosleep(64); }
        }
        __threadfence();
    }
    __syncthreads();
}

// ---------------------------------------------------------------------------
// helpers
// ---------------------------------------------------------------------------
__device__ __forceinline__ uint32_t f2tf(float x) {
    uint32_t r; asm("cvt.rna.tf32.f32 %0, %1;" : "=r"(r) : "f"(x)); return r;
}
__device__ __forceinline__ void mma8(float* d, const uint32_t* a, const uint32_t* b) {
    asm volatile(
        "mma.sync.aligned.m16n8k8.row.col.f32.tf32.tf32.f32 "
        "{%0,%1,%2,%3}, {%4,%5,%6,%7}, {%8,%9}, {%0,%1,%2,%3};"
        : "+f"(d[0]), "+f"(d[1]), "+f"(d[2]), "+f"(d[3])
        : "r"(a[0]), "r"(a[1]), "r"(a[2]), "r"(a[3]), "r"(b[0]), "r"(b[1]));
}

// ---------------------------------------------------------------------------
// TF32 mma.sync GEMM device fn (R7 layout): C[z][m,n] = sum_k A[m,k]*B[n,k]
// Tile 128x128, Kc=32 per stage, double-buffered smem, 256 threads / 8 warps.
// ---------------------------------------------------------------------------
#define ASZ    4608          // 128*36 words (ATR uses 32*132=4224 of it)
#define BSZ    4608
#define STAGE  (ASZ + BSZ)
#define SMEM_WORDS (2 * STAGE)
#define SMEM_BYTES (SMEM_WORDS * 4)

template<bool ATR, int LDA, int LDB, int MTOT, int NTOT, int KCHUNK>
__device__ __forceinline__ void gemm_dev(const float* __restrict__ Ag,
                                         const float* __restrict__ Bg,
                                         float* __restrict__ C,
                                         uint32_t* smem,
                                         int bx, int by, int bz) {
    const int t = threadIdx.x;
    const int nBase = bx * 128;
    const int mBase = by * 128;
    const int kb    = bz * KCHUNK;

    const bool isA = (t < 128);
    const int tt = t & 127;
    const int rr = tt >> 3;
    const int fc = tt & 7;
    const int jq = tt & 31;
    const int kr = tt >> 5;

    constexpr int NS = KCHUNK / 32;
    float4 rg[8];

#define LDG(s)                                                                  \
    {                                                                           \
        if (isA) {                                                              \
            if (ATR) {                                                          \
                _Pragma("unroll")                                               \
                for (int i = 0; i < 8; ++i)                                     \
                    rg[i] = *(const float4*)&Ag[(size_t)(kb + (s)*32 + kr + 4*i) * LDA \
                                                + mBase + jq * 4];              \
            } else {                                                            \
                _Pragma("unroll")                                               \
                for (int i = 0; i < 8; ++i)                                     \
                    rg[i] = *(const float4*)&Ag[(size_t)(mBase + rr + 16*i) * LDA \
                                                + kb + (s)*32 + fc * 4];        \
            }                                                                   \
        } else {                                                                \
            _Pragma("unroll")                                                   \
            for (int i = 0; i < 8; ++i)                                         \
                rg[i] = *(const float4*)&Bg[(size_t)(nBase + rr + 16*i) * LDB   \
                                            + kb + (s)*32 + fc * 4];            \
        }                                                                       \
    }

    const int w = t >> 5, lane = t & 31;
    const int moff = (w & 3) * 32;
    const int noff = (w >> 2) * 64;
    const int g = lane >> 2, q = lane & 3;

    float acc[2][8][4];
#pragma unroll
    for (int mt = 0; mt < 2; mt++)
#pragma unroll
        for (int nt = 0; nt < 8; nt++)
#pragma unroll
            for (int r = 0; r < 4; r++) acc[mt][nt][r] = 0.0f;

    LDG(0);

    for (int s = 0; s < NS; ++s) {
        const int buf = s & 1;
        uint32_t* dst = smem + buf * STAGE + (isA ? 0 : ASZ);
        if (isA && ATR) {
#pragma unroll
            for (int i = 0; i < 8; ++i) {
                uint32_t* p = dst + (kr + 4 * i) * 132 + jq * 4;
                p[0] = f2tf(rg[i].x); p[1] = f2tf(rg[i].y);
                p[2] = f2tf(rg[i].z); p[3] = f2tf(rg[i].w);
            }
        } else {
#pragma unroll
            for (int i = 0; i < 8; ++i) {
                uint32_t* p = dst + (rr + 16 * i) * 36 + fc * 4;
                p[0] = f2tf(rg[i].x); p[1] = f2tf(rg[i].y);
                p[2] = f2tf(rg[i].z); p[3] = f2tf(rg[i].w);
            }
        }
        __syncthreads();
        if (s + 1 < NS) LDG(s + 1);

        const uint32_t* As = smem + buf * STAGE;
        const uint32_t* Bs = As + ASZ;
#pragma unroll
        for (int k0 = 0; k0 < 32; k0 += 8) {
            uint32_t af[2][4];
#pragma unroll
            for (int mt = 0; mt < 2; mt++) {
                const int m0 = moff + mt * 16 + g;
                if (ATR) {
                    af[mt][0] = As[(k0 + q) * 132 + m0];
                    af[mt][1] = As[(k0 + q) * 132 + m0 + 8];
                    af[mt][2] = As[(k0 + q + 4) * 132 + m0];
                    af[mt][3] = As[(k0 + q + 4) * 132 + m0 + 8];
                } else {
                    af[mt][0] = As[m0 * 36 + k0 + q];
                    af[mt][1] = As[(m0 + 8) * 36 + k0 + q];
                    af[mt][2] = As[m0 * 36 + k0 + q + 4];
                    af[mt][3] = As[(m0 + 8) * 36 + k0 + q + 4];
                }
            }
            uint32_t bf[8][2];
#pragma unroll
            for (int nt = 0; nt < 8; nt++) {
                const int n0 = noff + nt * 8 + g;
                bf[nt][0] = Bs[n0 * 36 + k0 + q];
                bf[nt][1] = Bs[n0 * 36 + k0 + q + 4];
            }
#pragma unroll
            for (int mt = 0; mt < 2; mt++)
#pragma unroll
                for (int nt = 0; nt < 8; nt++)
                    mma8(acc[mt][nt], af[mt], bf[nt]);
        }
        __syncthreads();
    }
#undef LDG

    float* cz = C + (size_t)bz * MTOT * NTOT;
#pragma unroll
    for (int mt = 0; mt < 2; mt++) {
        const int r0 = mBase + moff + mt * 16 + g;
#pragma unroll
        for (int nt = 0; nt < 8; nt++) {
            const int c0 = nBase + noff + nt * 8 + q * 2;
            float2 v0 = make_float2(acc[mt][nt][0], acc[mt][nt][1]);
            float2 v1 = make_float2(acc[mt][nt][2], acc[mt][nt][3]);
            *(float2*)&cz[(size_t)r0 * NTOT + c0] = v0;
            *(float2*)&cz[(size_t)(r0 + 8) * NTOT + c0] = v1;
        }
    }
}

// ---------------------------------------------------------------------------
// Single mega-kernel, 256 blocks, 2 blocks/SM.
// P0 gemm_w | P1 reduce_w + bias_c | P2 gemm_temp |
// P34: temp chunk in registers, then stream all 50 L-slots of momery.
// ---------------------------------------------------------------------------
__global__ __launch_bounds__(256, 2) void k_all(const float* __restrict__ wo,
                                                const float* __restrict__ wv,
                                                const float* __restrict__ hid,
                                                const float* __restrict__ bv,
                                                const float* __restrict__ bo,
                                                const float* __restrict__ wsc,
                                                const float4* __restrict__ mom,
                                                float4* __restrict__ out) {
    extern __shared__ uint32_t smem[];
    __shared__ float sred[8];
    const int b = blockIdx.x;
    const int t = threadIdx.x;

    // ---- P0: Wt partials  Wt[j,a] = sum_k wo[k,j] * wv[a,k]
    gemm_dev<true, DD, HK, DD, DD, HK / KSW>(wo, wv, g_Wpart, smem,
                                             b & 3, (b >> 2) & 3, b >> 4);
    grid_bar();

    // ---- P1a: reduce W partials (65536 float4 over 256 blocks => 1/thread)
    {
        const float4* p = (const float4*)g_Wpart;
        int i = b * 256 + t;
        float4 s = p[i];
#pragma unroll
        for (int k = 1; k < KSW; k++) {
            float4 v = p[k * (DD * DD / 4) + i];
            s.x += v.x; s.y += v.y; s.z += v.z; s.w += v.w;
        }
        ((float4*)g_W)[i] = s;
    }
    // ---- P1b: bias c[j] = sum_k bv[k]*wo[k,j] + bo[j]  (2 j's per block)
    {
        const int jloc = t >> 7;               // 0..1
        const int j = b * 2 + jloc;
        const int tk = t & 127;
        float acc = 0.0f;
        const int k0 = tk * 16;
        for (int k = k0; k < k0 + 16; k++)
            acc += bv[k] * wo[(size_t)k * DD + j];
#pragma unroll
        for (int off = 16; off > 0; off >>= 1)
            acc += __shfl_down_sync(0xFFFFFFFFu, acc, off);
        if ((t & 31) == 0) sred[t >> 5] = acc;
        __syncthreads();
        if (t < 2)
            g_c[b * 2 + t] = sred[4 * t] + sred[4 * t + 1] + sred[4 * t + 2]
                           + sred[4 * t + 3] + bo[b * 2 + t];
    }
    grid_bar();

    // ---- P2: temp partials  Tpart[z][b,j] = sum_a hid[b,a]*Wt[j,a]
    gemm_dev<false, DD, DD, NB, DD, DD / KST>(hid, g_W, g_Tpart, smem,
                                              b & 3, (b >> 2) & 7, b >> 5);
    grid_bar();

    // ---- P34: temp chunk (2 float4/thread) into registers, then stream add.
    {
        const float sc = 3.0f * wsc[0];
        const float4* p = (const float4*)g_Tpart;
        float4 T[2];
        int idx0 = b * 512 + t;            // u=0 chunk
        int idx1 = idx0 + 256;             // u=1 chunk
#pragma unroll
        for (int u = 0; u < 2; ++u) {
            int i = (u == 0) ? idx0 : idx1;
            float4 s = p[i];
#pragma unroll
            for (int k = 1; k < KST; k++) {
                float4 v = p[k * BD4 + i];
                s.x += v.x; s.y += v.y; s.z += v.z; s.w += v.w;
            }
            float4 c4 = ((const float4*)g_c)[i & (DD / 4 - 1)];
            T[u].x = sc * (s.x + c4.x); T[u].y = sc * (s.y + c4.y);
            T[u].z = sc * (s.z + c4.z); T[u].w = sc * (s.w + c4.w);
        }

        // 50 L-slots, 4-way unrolled: 8 loads in flight per thread
#pragma unroll 1
        for (int l0 = 0; l0 < 48; l0 += 4) {
            size_t base = (size_t)l0 * BD4;
            float4 m00 = __ldcs(&mom[base + idx0]);
            float4 m01 = __ldcs(&mom[base + idx1]);
            float4 m10 = __ldcs(&mom[base + BD4 + idx0]);
            float4 m11 = __ldcs(&mom[base + BD4 + idx1]);
            float4 m20 = __ldcs(&mom[base + 2 * BD4 + idx0]);
            float4 m21 = __ldcs(&mom[base + 2 * BD4 + idx1]);
            float4 m30 = __ldcs(&mom[base + 3 * BD4 + idx0]);
            float4 m31 = __ldcs(&mom[base + 3 * BD4 + idx1]);
            m00.x += T[0].x; m00.y += T[0].y; m00.z += T[0].z; m00.w += T[0].w;
            m01.x += T[1].x; m01.y += T[1].y; m01.z += T[1].z; m01.w += T[1].w;
            m10.x += T[0].x; m10.y += T[0].y; m10.z += T[0].z; m10.w += T[0].w;
            m11.x += T[1].x; m11.y += T[1].y; m11.z += T[1].z; m11.w += T[1].w;
            m20.x += T[0].x; m20.y += T[0].y; m20.z += T[0].z; m20.w += T[0].w;
            m21.x += T[1].x; m21.y += T[1].y; m21.z += T[1].z; m21.w += T[1].w;
            m30.x += T[0].x; m30.y += T[0].y; m30.z += T[0].z; m30.w += T[0].w;
            m31.x += T[1].x; m31.y += T[1].y; m31.z += T[1].z; m31.w += T[1].w;
            __stcs(&out[base + idx0], m00);
            __stcs(&out[base + idx1], m01);
            __stcs(&out[base + BD4 + idx0], m10);
            __stcs(&out[base + BD4 + idx1], m11);
            __stcs(&out[base + 2 * BD4 + idx0], m20);
            __stcs(&out[base + 2 * BD4 + idx1], m21);
            __stcs(&out[base + 3 * BD4 + idx0], m30);
            __stcs(&out[base + 3 * BD4 + idx1], m31);
        }
        // remainder l = 48, 49
        {
            size_t base = (size_t)48 * BD4;
            float4 m00 = __ldcs(&mom[base + idx0]);
            float4 m01 = __ldcs(&mom[base + idx1]);
            float4 m10 = __ldcs(&mom[base + BD4 + idx0]);
            float4 m11 = __ldcs(&mom[base + BD4 + idx1]);
            m00.x += T[0].x; m00.y += T[0].y; m00.z += T[0].z; m00.w += T[0].w;
            m01.x += T[1].x; m01.y += T[1].y; m01.z += T[1].z; m01.w += T[1].w;
            m10.x += T[0].x; m10.y += T[0].y; m10.z += T[0].z; m10.w += T[0].w;
            m11.x += T[1].x; m11.y += T[1].y; m11.z += T[1].z; m11.w += T[1].w;
            __stcs(&out[base + idx0], m00);
            __stcs(&out[base + idx1], m01);
            __stcs(&out[base + BD4 + idx0], m10);
            __stcs(&out[base + BD4 + idx1], m11);
        }
    }
}

// ---------------------------------------------------------------------------
// Launch. Inputs (metadata order):
// 0 momery, 1 hid, 2 text_polarity, 3 attribute_polarity, 4 w,
// 5 p_w1, 6 p_b1, 7 p_w2, 8 p_b2, 9 wq, 10 bq, 11 wk, 12 bk,
// 13 wv, 14 bv, 15 wo, 16 bo
// ---------------------------------------------------------------------------
extern "C" void kernel_launch(void* const* d_in, const int* in_sizes, int n_in,
                              void* d_out, int out_size) {
    const float* momery = (const float*)d_in[0];
    const float* hid    = (const float*)d_in[1];
    const float* w      = (const float*)d_in[4];
    const float* wv     = (const float*)d_in[13];
    const float* bv     = (const float*)d_in[14];
    const float* wo     = (const float*)d_in[15];
    const float* bo     = (const float*)d_in[16];
    float* out = (float*)d_out;

    cudaFuncSetAttribute(k_all, cudaFuncAttributeMaxDynamicSharedMemorySize,
                         SMEM_BYTES);

    k_all<<<NBLK, 256, SMEM_BYTES>>>(wo, wv, hid, bv, bo, w,
                                     (const float4*)momery, (float4*)out);
}

// round 11
// speedup vs baseline: 1.1246x; 1.0254x over previous
#include <cuda_runtime.h>
#include <cstdint>

#define DD      512
#define HK      2048
#define NB      1024
#define LSLOTS  50
#define KSW     16           // split-K for W gemm
#define NBLK    256          // blocks in grid barrier
#define BD4     (NB * DD / 4)            // 131072 float4 per L-slot

// Scratch (static device globals — no allocation)
__device__ float g_Wpart[KSW * DD * DD];     // split-K partials of Wt[j,a] (16 MB)
__device__ float g_W[DD * DD];               // Wt[j][a] = (wv@wo)[a][j]
__device__ float g_c[DD];                    // bv@wo + bo

// grid barrier state (generation persists across replays; monotone)
__device__ int g_bar_count = 0;
__device__ volatile int g_bar_gen = 0;

__device__ __forceinline__ void grid_bar() {
    __syncthreads();
    if (threadIdx.x == 0) {
        __threadfence();
        int gen = g_bar_gen;
        if (atomicAdd(&g_bar_count, 1) == NBLK - 1) {
            g_bar_count = 0;
            __threadfence();
            g_bar_gen = gen + 1;
        } else {
            while (g_bar_gen == gen) { __nanosleep(64); }
        }
        __threadfence();
    }
    __syncthreads();
}

// ---------------------------------------------------------------------------
// helpers
// ---------------------------------------------------------------------------
__device__ __forceinline__ uint32_t f2tf(float x) {
    uint32_t r; asm("cvt.rna.tf32.f32 %0, %1;" : "=r"(r) : "f"(x)); return r;
}
__device__ __forceinline__ void mma8(float* d, const uint32_t* a, const uint32_t* b) {
    asm volatile(
        "mma.sync.aligned.m16n8k8.row.col.f32.tf32.tf32.f32 "
        "{%0,%1,%2,%3}, {%4,%5,%6,%7}, {%8,%9}, {%0,%1,%2,%3};"
        : "+f"(d[0]), "+f"(d[1]), "+f"(d[2]), "+f"(d[3])
        : "r"(a[0]), "r"(a[1]), "r"(a[2]), "r"(a[3]), "r"(b[0]), "r"(b[1]));
}

// ---------------------------------------------------------------------------
// P0 GEMM (unchanged R7/R10 layout): Wt partials, tile 128x128, Kc=32.
// ---------------------------------------------------------------------------
#define ASZ    4608
#define BSZ    4608
#define STAGE  (ASZ + BSZ)
#define SMEM_WORDS (2 * STAGE)           // 18432 words = 72 KB
#define SMEM_BYTES (SMEM_WORDS * 4)

template<int LDA, int LDB, int MTOT, int NTOT, int KCHUNK>
__device__ __forceinline__ void gemm_w_dev(const float* __restrict__ Ag,
                                           const float* __restrict__ Bg,
                                           float* __restrict__ C,
                                           uint32_t* smem,
                                           int bx, int by, int bz) {
    const int t = threadIdx.x;
    const int nBase = bx * 128;
    const int mBase = by * 128;
    const int kb    = bz * KCHUNK;

    const bool isA = (t < 128);
    const int tt = t & 127;
    const int rr = tt >> 3;
    const int fc = tt & 7;
    const int jq = tt & 31;
    const int kr = tt >> 5;

    constexpr int NS = KCHUNK / 32;
    float4 rg[8];

#define LDG(s)                                                                  \
    {                                                                           \
        if (isA) {                                                              \
            _Pragma("unroll")                                                   \
            for (int i = 0; i < 8; ++i)                                         \
                rg[i] = *(const float4*)&Ag[(size_t)(kb + (s)*32 + kr + 4*i) * LDA \
                                            + mBase + jq * 4];                  \
        } else {                                                                \
            _Pragma("unroll")                                                   \
            for (int i = 0; i < 8; ++i)                                         \
                rg[i] = *(const float4*)&Bg[(size_t)(nBase + rr + 16*i) * LDB   \
                                            + kb + (s)*32 + fc * 4];            \
        }                                                                       \
    }

    const int w = t >> 5, lane = t & 31;
    const int moff = (w & 3) * 32;
    const int noff = (w >> 2) * 64;
    const int g = lane >> 2, q = lane & 3;

    float acc[2][8][4];
#pragma unroll
    for (int mt = 0; mt < 2; mt++)
#pragma unroll
        for (int nt = 0; nt < 8; nt++)
#pragma unroll
            for (int r = 0; r < 4; r++) acc[mt][nt][r] = 0.0f;

    LDG(0);

    for (int s = 0; s < NS; ++s) {
        const int buf = s & 1;
        uint32_t* dst = smem + buf * STAGE + (isA ? 0 : ASZ);
        if (isA) {
#pragma unroll
            for (int i = 0; i < 8; ++i) {
                uint32_t* p = dst + (kr + 4 * i) * 132 + jq * 4;
                p[0] = f2tf(rg[i].x); p[1] = f2tf(rg[i].y);
                p[2] = f2tf(rg[i].z); p[3] = f2tf(rg[i].w);
            }
        } else {
#pragma unroll
            for (int i = 0; i < 8; ++i) {
                uint32_t* p = dst + (rr + 16 * i) * 36 + fc * 4;
                p[0] = f2tf(rg[i].x); p[1] = f2tf(rg[i].y);
                p[2] = f2tf(rg[i].z); p[3] = f2tf(rg[i].w);
            }
        }
        __syncthreads();
        if (s + 1 < NS) LDG(s + 1);

        const uint32_t* As = smem + buf * STAGE;
        const uint32_t* Bs = As + ASZ;
#pragma unroll
        for (int k0 = 0; k0 < 32; k0 += 8) {
            uint32_t af[2][4];
#pragma unroll
            for (int mt = 0; mt < 2; mt++) {
                const int m0 = moff + mt * 16 + g;
                af[mt][0] = As[(k0 + q) * 132 + m0];
                af[mt][1] = As[(k0 + q) * 132 + m0 + 8];
                af[mt][2] = As[(k0 + q + 4) * 132 + m0];
                af[mt][3] = As[(k0 + q + 4) * 132 + m0 + 8];
            }
            uint32_t bf[8][2];
#pragma unroll
            for (int nt = 0; nt < 8; nt++) {
                const int n0 = noff + nt * 8 + g;
                bf[nt][0] = Bs[n0 * 36 + k0 + q];
                bf[nt][1] = Bs[n0 * 36 + k0 + q + 4];
            }
#pragma unroll
            for (int mt = 0; mt < 2; mt++)
#pragma unroll
                for (int nt = 0; nt < 8; nt++)
                    mma8(acc[mt][nt], af[mt], bf[nt]);
        }
        __syncthreads();
    }
#undef LDG

    float* cz = C + (size_t)bz * MTOT * NTOT;
#pragma unroll
    for (int mt = 0; mt < 2; mt++) {
        const int r0 = mBase + moff + mt * 16 + g;
#pragma unroll
        for (int nt = 0; nt < 8; nt++) {
            const int c0 = nBase + noff + nt * 8 + q * 2;
            float2 v0 = make_float2(acc[mt][nt][0], acc[mt][nt][1]);
            float2 v1 = make_float2(acc[mt][nt][2], acc[mt][nt][3]);
            *(float2*)&cz[(size_t)r0 * NTOT + c0] = v0;
            *(float2*)&cz[(size_t)(r0 + 8) * NTOT + c0] = v1;
        }
    }
}

// ---------------------------------------------------------------------------
// Mega-kernel, 256 blocks, 2 blocks/SM.
// P0 gemm_w (16 tiles x 16 k-slices) | bar | P1 reduce_w + bias_c | bar |
// P2' per-tile full-K temp GEMM (64x32, K=512) -> smem tile ->
//     stream add over all 50 L-slots of that tile (NO barrier, NO temp global).
// ---------------------------------------------------------------------------
__global__ __launch_bounds__(256, 2) void k_all(const float* __restrict__ wo,
                                                const float* __restrict__ wv,
                                                const float* __restrict__ hid,
                                                const float* __restrict__ bv,
                                                const float* __restrict__ bo,
                                                const float* __restrict__ wsc,
                                                const float4* __restrict__ mom,
                                                float4* __restrict__ out) {
    extern __shared__ uint32_t smem[];
    __shared__ float sred[8];
    const int b = blockIdx.x;
    const int t = threadIdx.x;

    // ---- P0: Wt partials  Wt[j,a] = sum_k wo[k,j] * wv[a,k]
    gemm_w_dev<DD, HK, DD, DD, HK / KSW>(wo, wv, g_Wpart, smem,
                                         b & 3, (b >> 2) & 3, b >> 4);
    grid_bar();

    // ---- P1a: reduce W partials (65536 float4 over 256 blocks => 1/thread)
    {
        const float4* p = (const float4*)g_Wpart;
        int i = b * 256 + t;
        float4 s = p[i];
#pragma unroll
        for (int k = 1; k < KSW; k++) {
            float4 v = p[k * (DD * DD / 4) + i];
            s.x += v.x; s.y += v.y; s.z += v.z; s.w += v.w;
        }
        ((float4*)g_W)[i] = s;
    }
    // ---- P1b: bias c[j] = sum_k bv[k]*wo[k,j] + bo[j]  (2 j's per block)
    {
        const int jloc = t >> 7;               // 0..1
        const int j = b * 2 + jloc;
        const int tk = t & 127;
        float acc = 0.0f;
        const int k0 = tk * 16;
        for (int k = k0; k < k0 + 16; k++)
            acc += bv[k] * wo[(size_t)k * DD + j];
#pragma unroll
        for (int off = 16; off > 0; off >>= 1)
            acc += __shfl_down_sync(0xFFFFFFFFu, acc, off);
        if ((t & 31) == 0) sred[t >> 5] = acc;
        __syncthreads();
        if (t < 2)
            g_c[b * 2 + t] = sred[4 * t] + sred[4 * t + 1] + sred[4 * t + 2]
                           + sred[4 * t + 3] + bo[b * 2 + t];
    }
    grid_bar();

    // ---- P2': per-tile temp GEMM (64 b-rows x 32 j-cols, full K=512)
    // tile: bm = b & 15 (rows 64*bm), bn = b >> 4 (cols 32*bn)
    {
        const int mBase = (b & 15) * 64;
        const int nBase = (b >> 4) * 32;
        const int kq = t & 15, r0 = t >> 4;      // loader map
        const int w = t >> 5, lane = t & 31;
        const int moff = (w & 3) * 16;           // 4 m-quarters of 16
        const int noff = (w >> 2) * 16;          // 2 n-halves of 16
        const int g = lane >> 2, q = lane & 3;

        // stage: A[64][68] + B[32][68] words; double buffered
        constexpr int APITCH = 68;
        constexpr int BOFF = 64 * APITCH;                 // 4352
        constexpr int P2STAGE = BOFF + 32 * APITCH;       // 6528

        float acc[2][4];
#pragma unroll
        for (int nt = 0; nt < 2; nt++)
#pragma unroll
            for (int r = 0; r < 4; r++) acc[nt][r] = 0.0f;

        float4 ra[4], rb[2];

#define LDG2(s)                                                                 \
        {                                                                       \
            _Pragma("unroll")                                                   \
            for (int i = 0; i < 4; ++i)                                         \
                ra[i] = *(const float4*)&hid[(size_t)(mBase + r0 + 16*i) * DD   \
                                             + (s)*64 + kq * 4];                \
            _Pragma("unroll")                                                   \
            for (int i = 0; i < 2; ++i)                                         \
                rb[i] = *(const float4*)&g_W[(size_t)(nBase + r0 + 16*i) * DD   \
                                             + (s)*64 + kq * 4];                \
        }

        LDG2(0);
        for (int s = 0; s < 8; ++s) {
            const int buf = s & 1;
            uint32_t* dst = smem + buf * P2STAGE;
#pragma unroll
            for (int i = 0; i < 4; ++i) {
                uint32_t* p = dst + (r0 + 16 * i) * APITCH + kq * 4;
                p[0] = f2tf(ra[i].x); p[1] = f2tf(ra[i].y);
                p[2] = f2tf(ra[i].z); p[3] = f2tf(ra[i].w);
            }
#pragma unroll
            for (int i = 0; i < 2; ++i) {
                uint32_t* p = dst + BOFF + (r0 + 16 * i) * APITCH + kq * 4;
                p[0] = f2tf(rb[i].x); p[1] = f2tf(rb[i].y);
                p[2] = f2tf(rb[i].z); p[3] = f2tf(rb[i].w);
            }
            __syncthreads();
            if (s + 1 < 8) LDG2(s + 1);

            const uint32_t* As = smem + buf * P2STAGE;
            const uint32_t* Bs = As + BOFF;
#pragma unroll
            for (int k0 = 0; k0 < 64; k0 += 8) {
                uint32_t af[4];
                const int m0 = moff + g;
                af[0] = As[m0 * APITCH + k0 + q];
                af[1] = As[(m0 + 8) * APITCH + k0 + q];
                af[2] = As[m0 * APITCH + k0 + q + 4];
                af[3] = As[(m0 + 8) * APITCH + k0 + q + 4];
                uint32_t bf[2][2];
#pragma unroll
                for (int nt = 0; nt < 2; nt++) {
                    const int n0 = noff + nt * 8 + g;
                    bf[nt][0] = Bs[n0 * APITCH + k0 + q];
                    bf[nt][1] = Bs[n0 * APITCH + k0 + q + 4];
                }
                mma8(acc[0], af, bf[0]);
                mma8(acc[1], af, bf[1]);
            }
            __syncthreads();
        }
#undef LDG2

        // epilogue: temp tile (64x32) with bias+scale into smem [64][36]
        float* ts = (float*)smem;
        const float sc = 3.0f * wsc[0];
#pragma unroll
        for (int nt = 0; nt < 2; nt++) {
            const int c0 = noff + nt * 8 + q * 2;
            const float cv0 = g_c[nBase + c0];
            const float cv1 = g_c[nBase + c0 + 1];
            ts[(moff + g) * 36 + c0]     = sc * (acc[nt][0] + cv0);
            ts[(moff + g) * 36 + c0 + 1] = sc * (acc[nt][1] + cv1);
            ts[(moff + g + 8) * 36 + c0]     = sc * (acc[nt][2] + cv0);
            ts[(moff + g + 8) * 36 + c0 + 1] = sc * (acc[nt][3] + cv1);
        }
        __syncthreads();

        // stream: out[l, mBase..+64, nBase..+32] for l = 0..49
        const int ri = t >> 3;          // 0..31 (rows ri, ri+32)
        const int jq = t & 7;           // float4 within 32-col row
        float4 T0 = *(const float4*)&ts[ri * 36 + jq * 4];
        float4 T1 = *(const float4*)&ts[(ri + 32) * 36 + jq * 4];
        const int nb4 = nBase >> 2;
        const int base0 = (mBase + ri) * (DD / 4) + nb4 + jq;
        const int base1 = (mBase + ri + 32) * (DD / 4) + nb4 + jq;

#pragma unroll 1
        for (int l = 0; l < LSLOTS; l += 5) {
            float4 m[10];
            int idx[10];
#pragma unroll
            for (int u = 0; u < 5; ++u) {
                idx[2 * u]     = (l + u) * BD4 + base0;
                idx[2 * u + 1] = (l + u) * BD4 + base1;
                m[2 * u]     = __ldcs(&mom[idx[2 * u]]);
                m[2 * u + 1] = __ldcs(&mom[idx[2 * u + 1]]);
            }
#pragma unroll
            for (int u = 0; u < 5; ++u) {
                m[2*u].x += T0.x; m[2*u].y += T0.y; m[2*u].z += T0.z; m[2*u].w += T0.w;
                m[2*u+1].x += T1.x; m[2*u+1].y += T1.y; m[2*u+1].z += T1.z; m[2*u+1].w += T1.w;
                __stcs(&out[idx[2 * u]], m[2 * u]);
                __stcs(&out[idx[2 * u + 1]], m[2 * u + 1]);
            }
        }
    }
}

// ---------------------------------------------------------------------------
// Launch. Inputs (metadata order):
// 0 momery, 1 hid, 2 text_polarity, 3 attribute_polarity, 4 w,
// 5 p_w1, 6 p_b1, 7 p_w2, 8 p_b2, 9 wq, 10 bq, 11 wk, 12 bk,
// 13 wv, 14 bv, 15 wo, 16 bo
// ---------------------------------------------------------------------------
extern "C" void kernel_launch(void* const* d_in, const int* in_sizes, int n_in,
                              void* d_out, int out_size) {
    const float* momery = (const float*)d_in[0];
    const float* hid    = (const float*)d_in[1];
    const float* w      = (const float*)d_in[4];
    const float* wv     = (const float*)d_in[13];
    const float* bv     = (const float*)d_in[14];
    const float* wo     = (const float*)d_in[15];
    const float* bo     = (const float*)d_in[16];
    float* out = (float*)d_out;

    cudaFuncSetAttribute(k_all, cudaFuncAttributeMaxDynamicSharedMemorySize,
                         SMEM_BYTES);

    k_all<<<NBLK, 256, SMEM_BYTES>>>(wo, wv, hid, bv, bo, w,
                                     (const float4*)momery, (float4*)out);
}

// round 12
// speedup vs baseline: 1.1601x; 1.0315x over previous
#include <cuda_runtime.h>
#include <cstdint>

#define DD      512
#define HK      2048
#define NB      1024
#define LSLOTS  50
#define KSW     16           // split-K for W gemm
#define NBLK    256          // total blocks (4 supergroups x 64)
#define GRP     64           // blocks per supergroup
#define BD4     (NB * DD / 4)            // 131072 float4 per L-slot

// Scratch (static device globals — no allocation)
__device__ float g_Wpart[KSW * DD * DD];     // split-K partials of Wt[j,a] (16 MB)
__device__ float g_W[DD * DD];               // Wt[j][a] = (wv@wo)[a][j]
__device__ float g_c[DD];                    // bv@wo + bo

// per-supergroup monotone sync counters: [phase][J]
__device__ unsigned g_sync[2 * 4];

__device__ __forceinline__ void group_sync(int J, int phase) {
    __syncthreads();
    if (threadIdx.x == 0) {
        __threadfence();
        unsigned* c = &g_sync[phase * 4 + J];
        unsigned old = atomicAdd(c, 1u);
        unsigned target = (old / GRP + 1u) * GRP;
        while (*(volatile unsigned*)c < target) { __nanosleep(32); }
        __threadfence();
    }
    __syncthreads();
}

// ---------------------------------------------------------------------------
// helpers
// ---------------------------------------------------------------------------
__device__ __forceinline__ uint32_t f2tf(float x) {
    uint32_t r; asm("cvt.rna.tf32.f32 %0, %1;" : "=r"(r) : "f"(x)); return r;
}
__device__ __forceinline__ void mma8(float* d, const uint32_t* a, const uint32_t* b) {
    asm volatile(
        "mma.sync.aligned.m16n8k8.row.col.f32.tf32.tf32.f32 "
        "{%0,%1,%2,%3}, {%4,%5,%6,%7}, {%8,%9}, {%0,%1,%2,%3};"
        : "+f"(d[0]), "+f"(d[1]), "+f"(d[2]), "+f"(d[3])
        : "r"(a[0]), "r"(a[1]), "r"(a[2]), "r"(a[3]), "r"(b[0]), "r"(b[1]));
}

// ---------------------------------------------------------------------------
// P0 GEMM (R7/R11 layout): Wt partials, tile 128x128, Kc=32, double-buffered.
// ---------------------------------------------------------------------------
#define ASZ    4608
#define BSZ    4608
#define STAGE  (ASZ + BSZ)
#define SMEM_WORDS (2 * STAGE)           // 18432 words = 72 KB
#define SMEM_BYTES (SMEM_WORDS * 4)

template<int LDA, int LDB, int MTOT, int NTOT, int KCHUNK>
__device__ __forceinline__ void gemm_w_dev(const float* __restrict__ Ag,
                                           const float* __restrict__ Bg,
                                           float* __restrict__ C,
                                           uint32_t* smem,
                                           int bx, int by, int bz) {
    const int t = threadIdx.x;
    const int nBase = bx * 128;
    const int mBase = by * 128;
    const int kb    = bz * KCHUNK;

    const bool isA = (t < 128);
    const int tt = t & 127;
    const int rr = tt >> 3;
    const int fc = tt & 7;
    const int jq = tt & 31;
    const int kr = tt >> 5;

    constexpr int NS = KCHUNK / 32;
    float4 rg[8];

#define LDG(s)                                                                  \
    {                                                                           \
        if (isA) {                                                              \
            _Pragma("unroll")                                                   \
            for (int i = 0; i < 8; ++i)                                         \
                rg[i] = *(const float4*)&Ag[(size_t)(kb + (s)*32 + kr + 4*i) * LDA \
                                            + mBase + jq * 4];                  \
        } else {                                                                \
            _Pragma("unroll")                                                   \
            for (int i = 0; i < 8; ++i)                                         \
                rg[i] = *(const float4*)&Bg[(size_t)(nBase + rr + 16*i) * LDB   \
                                            + kb + (s)*32 + fc * 4];            \
        }                                                                       \
    }

    const int w = t >> 5, lane = t & 31;
    const int moff = (w & 3) * 32;
    const int noff = (w >> 2) * 64;
    const int g = lane >> 2, q = lane & 3;

    float acc[2][8][4];
#pragma unroll
    for (int mt = 0; mt < 2; mt++)
#pragma unroll
        for (int nt = 0; nt < 8; nt++)
#pragma unroll
            for (int r = 0; r < 4; r++) acc[mt][nt][r] = 0.0f;

    LDG(0);

    for (int s = 0; s < NS; ++s) {
        const int buf = s & 1;
        uint32_t* dst = smem + buf * STAGE + (isA ? 0 : ASZ);
        if (isA) {
#pragma unroll
            for (int i = 0; i < 8; ++i) {
                uint32_t* p = dst + (kr + 4 * i) * 132 + jq * 4;
                p[0] = f2tf(rg[i].x); p[1] = f2tf(rg[i].y);
                p[2] = f2tf(rg[i].z); p[3] = f2tf(rg[i].w);
            }
        } else {
#pragma unroll
            for (int i = 0; i < 8; ++i) {
                uint32_t* p = dst + (rr + 16 * i) * 36 + fc * 4;
                p[0] = f2tf(rg[i].x); p[1] = f2tf(rg[i].y);
                p[2] = f2tf(rg[i].z); p[3] = f2tf(rg[i].w);
            }
        }
        __syncthreads();
        if (s + 1 < NS) LDG(s + 1);

        const uint32_t* As = smem + buf * STAGE;
        const uint32_t* Bs = As + ASZ;
#pragma unroll
        for (int k0 = 0; k0 < 32; k0 += 8) {
            uint32_t af[2][4];
#pragma unroll
            for (int mt = 0; mt < 2; mt++) {
                const int m0 = moff + mt * 16 + g;
                af[mt][0] = As[(k0 + q) * 132 + m0];
                af[mt][1] = As[(k0 + q) * 132 + m0 + 8];
                af[mt][2] = As[(k0 + q + 4) * 132 + m0];
                af[mt][3] = As[(k0 + q + 4) * 132 + m0 + 8];
            }
            uint32_t bf[8][2];
#pragma unroll
            for (int nt = 0; nt < 8; nt++) {
                const int n0 = noff + nt * 8 + g;
                bf[nt][0] = Bs[n0 * 36 + k0 + q];
                bf[nt][1] = Bs[n0 * 36 + k0 + q + 4];
            }
#pragma unroll
            for (int mt = 0; mt < 2; mt++)
#pragma unroll
                for (int nt = 0; nt < 8; nt++)
                    mma8(acc[mt][nt], af[mt], bf[nt]);
        }
        __syncthreads();
    }
#undef LDG

    float* cz = C + (size_t)bz * MTOT * NTOT;
#pragma unroll
    for (int mt = 0; mt < 2; mt++) {
        const int r0 = mBase + moff + mt * 16 + g;
#pragma unroll
        for (int nt = 0; nt < 8; nt++) {
            const int c0 = nBase + noff + nt * 8 + q * 2;
            float2 v0 = make_float2(acc[mt][nt][0], acc[mt][nt][1]);
            float2 v1 = make_float2(acc[mt][nt][2], acc[mt][nt][3]);
            *(float2*)&cz[(size_t)r0 * NTOT + c0] = v0;
            *(float2*)&cz[(size_t)(r0 + 8) * NTOT + c0] = v1;
        }
    }
}

// ---------------------------------------------------------------------------
// Mega-kernel, 256 blocks = 4 supergroups x 64, 2 blocks/SM.
// Supergroup J owns j-strip [128J, 128J+128) end-to-end:
//   P0 (4 a-tiles x 16 k-slices) | group sync | P1 reduce strip + bias |
//   group sync | P2' 64x32 temp tile (K=512) -> smem -> stream 50 L-slots.
// ---------------------------------------------------------------------------
__global__ __launch_bounds__(256, 2) void k_all(const float* __restrict__ wo,
                                                const float* __restrict__ wv,
                                                const float* __restrict__ hid,
                                                const float* __restrict__ bv,
                                                const float* __restrict__ bo,
                                                const float* __restrict__ wsc,
                                                const float4* __restrict__ mom,
                                                float4* __restrict__ out) {
    extern __shared__ uint32_t smem[];
    __shared__ float sred[8];
    const int b = blockIdx.x;
    const int t = threadIdx.x;
    const int J = b >> 6;           // supergroup 0..3 (j-strip 128J..)
    const int u = b & 63;           // member within supergroup

    // ---- P0: Wt partials for rows [128J, 128J+128): bx = u&3 (a-tile),
    //      by = J (j-tile), bz = u>>2 (k-slice 0..15)
    gemm_w_dev<DD, HK, DD, DD, HK / KSW>(wo, wv, g_Wpart, smem,
                                         u & 3, J, u >> 2);
    group_sync(J, 0);

    // ---- P1a: reduce this strip's W partials (16384 float4 / 64 blocks)
    {
        const float4* p = (const float4*)g_Wpart;
        int i = J * 16384 + u * 256 + t;
        float4 s = p[i];
#pragma unroll
        for (int k = 1; k < KSW; k++) {
            float4 v = p[k * (DD * DD / 4) + i];
            s.x += v.x; s.y += v.y; s.z += v.z; s.w += v.w;
        }
        ((float4*)g_W)[i] = s;
    }
    // ---- P1b: bias c[j] for this strip (2 j's per block)
    {
        const int jloc = t >> 7;               // 0..1
        const int j = J * 128 + u * 2 + jloc;
        const int tk = t & 127;
        float acc = 0.0f;
        const int k0 = tk * 16;
        for (int k = k0; k < k0 + 16; k++)
            acc += bv[k] * wo[(size_t)k * DD + j];
#pragma unroll
        for (int off = 16; off > 0; off >>= 1)
            acc += __shfl_down_sync(0xFFFFFFFFu, acc, off);
        if ((t & 31) == 0) sred[t >> 5] = acc;
        __syncthreads();
        if (t < 2)
            g_c[J * 128 + u * 2 + t] = sred[4 * t] + sred[4 * t + 1]
                                     + sred[4 * t + 2] + sred[4 * t + 3]
                                     + bo[J * 128 + u * 2 + t];
    }
    group_sync(J, 1);

    // ---- P2': temp tile (64 b-rows x 32 j-cols, full K=512), then stream.
    {
        const int mBase = (u & 15) * 64;
        const int nBase = J * 128 + (u >> 4) * 32;
        const int kq = t & 15, r0 = t >> 4;      // loader map
        const int w = t >> 5, lane = t & 31;
        const int moff = (w & 3) * 16;
        const int noff = (w >> 2) * 16;
        const int g = lane >> 2, q = lane & 3;

        constexpr int APITCH = 68;
        constexpr int BOFF = 64 * APITCH;                 // 4352
        constexpr int P2STAGE = BOFF + 32 * APITCH;       // 6528

        float acc[2][4];
#pragma unroll
        for (int nt = 0; nt < 2; nt++)
#pragma unroll
            for (int r = 0; r < 4; r++) acc[nt][r] = 0.0f;

        float4 ra[4], rb[2];

#define LDG2(s)                                                                 \
        {                                                                       \
            _Pragma("unroll")                                                   \
            for (int i = 0; i < 4; ++i)                                         \
                ra[i] = *(const float4*)&hid[(size_t)(mBase + r0 + 16*i) * DD   \
                                             + (s)*64 + kq * 4];                \
            _Pragma("unroll")                                                   \
            for (int i = 0; i < 2; ++i)                                         \
                rb[i] = *(const float4*)&g_W[(size_t)(nBase + r0 + 16*i) * DD   \
                                             + (s)*64 + kq * 4];                \
        }

        LDG2(0);
        for (int s = 0; s < 8; ++s) {
            const int buf = s & 1;
            uint32_t* dst = smem + buf * P2STAGE;
#pragma unroll
            for (int i = 0; i < 4; ++i) {
                uint32_t* p = dst + (r0 + 16 * i) * APITCH + kq * 4;
                p[0] = f2tf(ra[i].x); p[1] = f2tf(ra[i].y);
                p[2] = f2tf(ra[i].z); p[3] = f2tf(ra[i].w);
            }
#pragma unroll
            for (int i = 0; i < 2; ++i) {
                uint32_t* p = dst + BOFF + (r0 + 16 * i) * APITCH + kq * 4;
                p[0] = f2tf(rb[i].x); p[1] = f2tf(rb[i].y);
                p[2] = f2tf(rb[i].z); p[3] = f2tf(rb[i].w);
            }
            __syncthreads();
            if (s + 1 < 8) LDG2(s + 1);

            const uint32_t* As = smem + buf * P2STAGE;
            const uint32_t* Bs = As + BOFF;
#pragma unroll
            for (int k0 = 0; k0 < 64; k0 += 8) {
                uint32_t af[4];
                const int m0 = moff + g;
                af[0] = As[m0 * APITCH + k0 + q];
                af[1] = As[(m0 + 8) * APITCH + k0 + q];
                af[2] = As[m0 * APITCH + k0 + q + 4];
                af[3] = As[(m0 + 8) * APITCH + k0 + q + 4];
                uint32_t bf[2][2];
#pragma unroll
                for (int nt = 0; nt < 2; nt++) {
                    const int n0 = noff + nt * 8 + g;
                    bf[nt][0] = Bs[n0 * APITCH + k0 + q];
                    bf[nt][1] = Bs[n0 * APITCH + k0 + q + 4];
                }
                mma8(acc[0], af, bf[0]);
                mma8(acc[1], af, bf[1]);
            }
            __syncthreads();
        }
#undef LDG2

        // epilogue: temp tile (64x32) with bias+scale into smem [64][36]
        float* ts = (float*)smem;
        const float sc = 3.0f * wsc[0];
#pragma unroll
        for (int nt = 0; nt < 2; nt++) {
            const int c0 = noff + nt * 8 + q * 2;
            const float cv0 = g_c[nBase + c0];
            const float cv1 = g_c[nBase + c0 + 1];
            ts[(moff + g) * 36 + c0]     = sc * (acc[nt][0] + cv0);
            ts[(moff + g) * 36 + c0 + 1] = sc * (acc[nt][1] + cv1);
            ts[(moff + g + 8) * 36 + c0]     = sc * (acc[nt][2] + cv0);
            ts[(moff + g + 8) * 36 + c0 + 1] = sc * (acc[nt][3] + cv1);
        }
        __syncthreads();

        // stream: out[l, mBase..+64, nBase..+32] for l = 0..49
        const int ri = t >> 3;          // 0..31 (rows ri, ri+32)
        const int jq2 = t & 7;          // float4 within 32-col row
        float4 T0 = *(const float4*)&ts[ri * 36 + jq2 * 4];
        float4 T1 = *(const float4*)&ts[(ri + 32) * 36 + jq2 * 4];
        const int nb4 = nBase >> 2;
        const int base0 = (mBase + ri) * (DD / 4) + nb4 + jq2;
        const int base1 = (mBase + ri + 32) * (DD / 4) + nb4 + jq2;

#pragma unroll 1
        for (int l = 0; l < LSLOTS; l += 5) {
            float4 m[10];
            int idx[10];
#pragma unroll
            for (int v = 0; v < 5; ++v) {
                idx[2 * v]     = (l + v) * BD4 + base0;
                idx[2 * v + 1] = (l + v) * BD4 + base1;
                m[2 * v]     = __ldcs(&mom[idx[2 * v]]);
                m[2 * v + 1] = __ldcs(&mom[idx[2 * v + 1]]);
            }
#pragma unroll
            for (int v = 0; v < 5; ++v) {
                m[2*v].x += T0.x; m[2*v].y += T0.y; m[2*v].z += T0.z; m[2*v].w += T0.w;
                m[2*v+1].x += T1.x; m[2*v+1].y += T1.y; m[2*v+1].z += T1.z; m[2*v+1].w += T1.w;
                __stcs(&out[idx[2 * v]], m[2 * v]);
                __stcs(&out[idx[2 * v + 1]], m[2 * v + 1]);
            }
        }
    }
}

// ---------------------------------------------------------------------------
// Launch. Inputs (metadata order):
// 0 momery, 1 hid, 2 text_polarity, 3 attribute_polarity, 4 w,
// 5 p_w1, 6 p_b1, 7 p_w2, 8 p_b2, 9 wq, 10 bq, 11 wk, 12 bk,
// 13 wv, 14 bv, 15 wo, 16 bo
// ---------------------------------------------------------------------------
extern "C" void kernel_launch(void* const* d_in, const int* in_sizes, int n_in,
                              void* d_out, int out_size) {
    const float* momery = (const float*)d_in[0];
    const float* hid    = (const float*)d_in[1];
    const float* w      = (const float*)d_in[4];
    const float* wv     = (const float*)d_in[13];
    const float* bv     = (const float*)d_in[14];
    const float* wo     = (const float*)d_in[15];
    const float* bo     = (const float*)d_in[16];
    float* out = (float*)d_out;

    cudaFuncSetAttribute(k_all, cudaFuncAttributeMaxDynamicSharedMemorySize,
                         SMEM_BYTES);

    k_all<<<NBLK, 256, SMEM_BYTES>>>(wo, wv, hid, bv, bo, w,
                                     (const float4*)momery, (float4*)out);
}